// round 7
// baseline (speedup 1.0000x reference)
#include <cuda_runtime.h>
#include <mma.h>
#include <math.h>

using namespace nvcuda;

#define Nn   768
#define NNt  (768*768)
#define PROJ 1152
#define CATD 2112

#define RS48 0.14433756729740643f   /* 1/sqrt(48) */
#define RS3  0.5773502691896258f    /* 1/sqrt(3)  */
#define RS54 0.13608276348795434f   /* 1/sqrt(54) */

#define LA_LD 772                   /* padded lda for attention smem */

/* ------------------------- scratch (device globals) ---------------------- */
__device__ float g_Wpack[384 * PROJ];
__device__ float g_bpack[PROJ];
__device__ float g_proj[Nn * PROJ];
__device__ float g_q [Nn * 192];
__device__ float g_k [Nn * 192];
__device__ float g_qp[Nn * 144];
__device__ float g_kp[Nn * 144];
__device__ float g_vc[12 * Nn * 48];        /* packed v(16) || vp(24) || pad8 */
__device__ float g_a [(size_t)12 * NNt];    /* logits -> attn (28.3 MB) */
__device__ float g_ptg[Nn * 12 * 24];       /* o_pt in global frame */
__device__ float g_cat[(size_t)Nn * CATD];

/* ---------------- 3xTF32 split-precision MMA helper ---------------------- */
typedef wmma::fragment<wmma::matrix_a, 16, 16, 8, wmma::precision::tf32, wmma::row_major> FragA;
typedef wmma::fragment<wmma::matrix_b, 16, 16, 8, wmma::precision::tf32, wmma::row_major> FragB;
typedef wmma::fragment<wmma::accumulator, 16, 16, 8, float> FragC;

__device__ __forceinline__ void mma3(FragC& cf,
                                     const float* aptr, int lda,
                                     const float* bptr, int ldb)
{
    FragA ah, al;
    FragB bh, bl;
    wmma::load_matrix_sync(ah, aptr, lda);
    wmma::load_matrix_sync(bh, bptr, ldb);
#pragma unroll
    for (int e = 0; e < ah.num_elements; e++) {
        float v = ah.x[e];
        float h = wmma::__float_to_tf32(v);
        ah.x[e] = h;
        al.x[e] = wmma::__float_to_tf32(v - h);
    }
#pragma unroll
    for (int e = 0; e < bh.num_elements; e++) {
        float v = bh.x[e];
        float h = wmma::__float_to_tf32(v);
        bh.x[e] = h;
        bl.x[e] = wmma::__float_to_tf32(v - h);
    }
    wmma::mma_sync(cf, ah, bl, cf);
    wmma::mma_sync(cf, al, bh, cf);
    wmma::mma_sync(cf, ah, bh, cf);
}

/* ------------------------- K0: pack projection weights ------------------- */
__global__ void k_pack(const float* __restrict__ Wq,  const float* __restrict__ Wkv,
                       const float* __restrict__ Wqp, const float* __restrict__ Wkvp,
                       const float* __restrict__ bq,  const float* __restrict__ bkv,
                       const float* __restrict__ bqp, const float* __restrict__ bkvp)
{
    int idx = blockIdx.x * blockDim.x + threadIdx.x;
    if (idx < 384 * PROJ) {
        int r = idx / PROJ, o = idx % PROJ;
        float v;
        if      (o < 192) v = Wq  [r * 192 + o];
        else if (o < 576) v = Wkv [r * 384 + (o - 192)];
        else if (o < 720) v = Wqp [r * 144 + (o - 576)];
        else              v = Wkvp[r * 432 + (o - 720)];
        g_Wpack[idx] = v;
    }
    if (idx < PROJ) {
        int o = idx;
        float v;
        if      (o < 192) v = bq  [o];
        else if (o < 576) v = bkv [o - 192];
        else if (o < 720) v = bqp [o - 576];
        else              v = bkvp[o - 720];
        g_bpack[o] = v;
    }
}

/* ------------------- K1: projection GEMM 768 x 1152 x 384 (fp32) --------- */
__global__ __launch_bounds__(256) void k_proj_gemm(const float* __restrict__ s)
{
    __shared__ float s_t[16][65];
    __shared__ float w_t[16][64];
    int o0 = blockIdx.x * 64, i0 = blockIdx.y * 64;
    int t  = threadIdx.x;
    int tx = t % 16, ty = t / 16;
    float acc[4][4];
#pragma unroll
    for (int a = 0; a < 4; a++)
#pragma unroll
        for (int b = 0; b < 4; b++) acc[a][b] = 0.f;

    for (int k0 = 0; k0 < 384; k0 += 16) {
        { int ii = t / 4, kc = (t % 4) * 4;
          float4 sv = *(const float4*)&s[(size_t)(i0 + ii) * 384 + k0 + kc];
          s_t[kc + 0][ii] = sv.x; s_t[kc + 1][ii] = sv.y;
          s_t[kc + 2][ii] = sv.z; s_t[kc + 3][ii] = sv.w; }
        { int kc = t / 16, oo = (t % 16) * 4;
          *(float4*)&w_t[kc][oo] =
              *(const float4*)&g_Wpack[(size_t)(k0 + kc) * PROJ + o0 + oo]; }
        __syncthreads();
#pragma unroll
        for (int kc = 0; kc < 16; kc++) {
            float sv[4];
#pragma unroll
            for (int a = 0; a < 4; a++) sv[a] = s_t[kc][ty * 4 + a];
            float4 w4 = *(float4*)&w_t[kc][tx * 4];
            float wv[4] = {w4.x, w4.y, w4.z, w4.w};
#pragma unroll
            for (int a = 0; a < 4; a++)
#pragma unroll
                for (int b = 0; b < 4; b++) acc[a][b] += sv[a] * wv[b];
        }
        __syncthreads();
    }
#pragma unroll
    for (int a = 0; a < 4; a++) {
        float4 o4;
        o4.x = acc[a][0] + g_bpack[o0 + tx * 4 + 0];
        o4.y = acc[a][1] + g_bpack[o0 + tx * 4 + 1];
        o4.z = acc[a][2] + g_bpack[o0 + tx * 4 + 2];
        o4.w = acc[a][3] + g_bpack[o0 + tx * 4 + 3];
        *(float4*)&g_proj[(size_t)(i0 + ty * 4 + a) * PROJ + o0 + tx * 4] = o4;
    }
}

/* -------------- K1b: reshape + rigid-frame rotation of points ------------ */
__global__ __launch_bounds__(192) void k_reshape(const float* __restrict__ rot,
                                                 const float* __restrict__ trans)
{
    int i = blockIdx.x, t = threadIdx.x;
    __shared__ float pr[PROJ];
    for (int idx = t; idx < PROJ; idx += 192) pr[idx] = g_proj[(size_t)i * PROJ + idx];
    __syncthreads();

    g_q[(size_t)i * 192 + t] = pr[t];
    for (int o = t; o < 384; o += 192) {
        int h = o / 32, w = o % 32;
        float v = pr[192 + o];
        if (w < 16) g_k[(size_t)i * 192 + h * 16 + w] = v;
        else        g_vc[(size_t)(h * Nn + i) * 48 + (w - 16)] = v;
    }
    /* zero the 8 pad columns of vc */
    for (int o = t; o < 96; o += 192) {
        int h = o / 8, c = 40 + (o % 8);
        g_vc[(size_t)(h * Nn + i) * 48 + c] = 0.f;
    }
    float R0 = rot[i*9+0], R1 = rot[i*9+1], R2 = rot[i*9+2];
    float R3 = rot[i*9+3], R4 = rot[i*9+4], R5 = rot[i*9+5];
    float R6 = rot[i*9+6], R7 = rot[i*9+7], R8 = rot[i*9+8];
    float T0 = trans[i*3+0], T1 = trans[i*3+1], T2 = trans[i*3+2];

    if (t < 48) {
        float v0 = pr[576 + t], v1 = pr[624 + t], v2 = pr[672 + t];
        float x = R0*v0 + R1*v1 + R2*v2 + T0;
        float y = R3*v0 + R4*v1 + R5*v2 + T1;
        float z = R6*v0 + R7*v1 + R8*v2 + T2;
        int base = i * 144 + t * 3;
        g_qp[base] = x; g_qp[base+1] = y; g_qp[base+2] = z;
    }
    if (t < 144) {
        float v0 = pr[720 + t], v1 = pr[864 + t], v2 = pr[1008 + t];
        float x = R0*v0 + R1*v1 + R2*v2 + T0;
        float y = R3*v0 + R4*v1 + R5*v2 + T1;
        float z = R6*v0 + R7*v1 + R8*v2 + T2;
        int h = t / 12, r = t % 12;
        if (r < 4) {
            int base = i * 144 + (h * 4 + r) * 3;
            g_kp[base] = x; g_kp[base+1] = y; g_kp[base+2] = z;
        } else {
            int base = (h * Nn + i) * 48 + 16 + (r - 4) * 3;
            g_vc[base] = x; g_vc[base+1] = y; g_vc[base+2] = z;
        }
    }
}

/* ---- K2a: logits = qk*rs48 + pt + mask + rs3*b_b   (64x64xh tiles) ------ */
__global__ __launch_bounds__(256) void k_logits(const float* __restrict__ mask,
                                                const float* __restrict__ hwraw,
                                                const float* __restrict__ b_b)
{
    __shared__ float q_sT[16][64], k_sT[16][64];
    __shared__ float qp_sT[12][64], kp_sT[12][64];
    __shared__ float mi_s[64], mj_s[64];
    __shared__ float hw_sh, bb_sh;
    int h = blockIdx.z, i0 = blockIdx.y * 64, j0 = blockIdx.x * 64;
    int t = threadIdx.x;

    { int ii = t / 4, c0 = (t % 4) * 4;
      float4 qv = *(const float4*)&g_q[(size_t)(i0 + ii) * 192 + h * 16 + c0];
      q_sT[c0+0][ii] = qv.x; q_sT[c0+1][ii] = qv.y; q_sT[c0+2][ii] = qv.z; q_sT[c0+3][ii] = qv.w;
      float4 kv = *(const float4*)&g_k[(size_t)(j0 + ii) * 192 + h * 16 + c0];
      k_sT[c0+0][ii] = kv.x; k_sT[c0+1][ii] = kv.y; k_sT[c0+2][ii] = kv.z; k_sT[c0+3][ii] = kv.w; }
    if (t < 192) {
      int ii = t / 3, c0 = (t % 3) * 4;
      float4 qv = *(const float4*)&g_qp[(size_t)(i0 + ii) * 144 + h * 12 + c0];
      qp_sT[c0+0][ii] = qv.x; qp_sT[c0+1][ii] = qv.y; qp_sT[c0+2][ii] = qv.z; qp_sT[c0+3][ii] = qv.w;
      float4 kv = *(const float4*)&g_kp[(size_t)(j0 + ii) * 144 + h * 12 + c0];
      kp_sT[c0+0][ii] = kv.x; kp_sT[c0+1][ii] = kv.y; kp_sT[c0+2][ii] = kv.z; kp_sT[c0+3][ii] = kv.w; }
    if (t < 64) { mi_s[t] = mask[i0 + t]; mj_s[t] = mask[j0 + t]; }
    if (t == 0) {
        hw_sh = log1pf(expf(hwraw[h])) * RS54;
        bb_sh = b_b[h] * RS3;
    }
    __syncthreads();

    int tx = t % 16, ty = t / 16;
    float acc[4][4], d2[4][4];
#pragma unroll
    for (int a = 0; a < 4; a++)
#pragma unroll
        for (int b = 0; b < 4; b++) { acc[a][b] = 0.f; d2[a][b] = 0.f; }

#pragma unroll
    for (int c = 0; c < 16; c++) {
        float qr[4];
#pragma unroll
        for (int a = 0; a < 4; a++) qr[a] = q_sT[c][ty * 4 + a];
        float4 k4 = *(float4*)&k_sT[c][tx * 4];
        float kr[4] = {k4.x, k4.y, k4.z, k4.w};
#pragma unroll
        for (int a = 0; a < 4; a++)
#pragma unroll
            for (int b = 0; b < 4; b++) acc[a][b] += qr[a] * kr[b];
    }
#pragma unroll
    for (int p = 0; p < 4; p++) {
        float qx[4], qy[4], qz[4], kx[4], ky[4], kz[4];
#pragma unroll
        for (int a = 0; a < 4; a++) {
            qx[a] = qp_sT[p*3+0][ty*4+a];
            qy[a] = qp_sT[p*3+1][ty*4+a];
            qz[a] = qp_sT[p*3+2][ty*4+a];
        }
#pragma unroll
        for (int b = 0; b < 4; b++) {
            kx[b] = kp_sT[p*3+0][tx*4+b];
            ky[b] = kp_sT[p*3+1][tx*4+b];
            kz[b] = kp_sT[p*3+2][tx*4+b];
        }
#pragma unroll
        for (int a = 0; a < 4; a++)
#pragma unroll
            for (int b = 0; b < 4; b++) {
                float dx = qx[a]-kx[b], dy = qy[a]-ky[b], dz = qz[a]-kz[b];
                d2[a][b] += dx*dx + dy*dy + dz*dz;
            }
    }
    float hw = hw_sh, bb = bb_sh;
#pragma unroll
    for (int a = 0; a < 4; a++) {
        float mi = mi_s[ty * 4 + a];
        float4 o4;
        o4.x = acc[a][0]*RS48 - 0.5f*hw*d2[a][0] + bb + 100000.0f*(mi*mj_s[tx*4+0] - 1.0f);
        o4.y = acc[a][1]*RS48 - 0.5f*hw*d2[a][1] + bb + 100000.0f*(mi*mj_s[tx*4+1] - 1.0f);
        o4.z = acc[a][2]*RS48 - 0.5f*hw*d2[a][2] + bb + 100000.0f*(mi*mj_s[tx*4+2] - 1.0f);
        o4.w = acc[a][3]*RS48 - 0.5f*hw*d2[a][3] + bb + 100000.0f*(mi*mj_s[tx*4+3] - 1.0f);
        *(float4*)&g_a[(size_t)h * NNt + (size_t)(i0 + ty*4 + a) * Nn + j0 + tx*4] = o4;
    }
}

/* ------ K2b: logits += rs3 * (z @ W_b)  via 3xtf32 wmma (z read #1) ------ */
__global__ __launch_bounds__(256) void k_bias_mma(const float* __restrict__ z,
                                                  const float* __restrict__ W_b)
{
    __shared__ float wb_s[128 * 20];        /* [k][n], ldb=20 */
    __shared__ float out_s[8 * 256];        /* per-warp 16x16 */
    int t = threadIdx.x, w = t / 32;
    size_t mbase = (size_t)blockIdx.x * 128;

    for (int idx = t; idx < 128 * 16; idx += 256) {
        int c = idx / 16, h = idx % 16;
        wb_s[c * 20 + h] = (h < 12) ? W_b[c * 12 + h] : 0.f;
    }
    __syncthreads();

    FragC cf;
    wmma::fill_fragment(cf, 0.f);

    const float* zrow = z + (mbase + (size_t)w * 16) * 128;
#pragma unroll
    for (int k0 = 0; k0 < 128; k0 += 8)
        mma3(cf, zrow + k0, 128, wb_s + k0 * 20, 20);

    wmma::store_matrix_sync(&out_s[w * 256], cf, 16, wmma::mem_row_major);
    __syncthreads();

    for (int idx = t; idx < 128 * 12; idx += 256) {
        int h = idx / 128, r = idx % 128;
        float val = out_s[(r / 16) * 256 + (r % 16) * 16 + h];
        g_a[(size_t)h * NNt + mbase + r] += RS3 * val;
    }
}

/* --- K3: fused weighted softmax + o_pair = a.z (3xtf32, z read #2) ------- */
__global__ __launch_bounds__(256) void k_soft_opair(const float* __restrict__ z,
                                                    const float* __restrict__ ss)
{
    extern __shared__ float dsm[];
    float* la    = dsm;                      /* 16 x LA_LD               */
    float* wrow  = dsm + 16 * LA_LD;         /* 768                      */
    float* outst = wrow + Nn;                /* 16 x 128                 */
    int i = blockIdx.x, t = threadIdx.x;

    for (int idx = t; idx < 12 * Nn; idx += 256) {
        int h = idx / Nn, j = idx % Nn;
        la[h * LA_LD + j] = g_a[(size_t)h * NNt + (size_t)i * Nn + j];
    }
    /* zero pad rows 12..15 (exactly 4*LA_LD floats, incl. their col pads) */
    for (int idx = t; idx < 4 * LA_LD; idx += 256)
        la[12 * LA_LD + idx] = 0.f;
    /* zero the 4 col-pad floats of rows 0..11 */
    if (t < 48) { int h = t / 4, c = t % 4; la[h * LA_LD + Nn + c] = 0.f; }
    for (int j = t; j < Nn; j += 256)
        wrow[j] = expf(ss[(size_t)i * Nn + j]) - 0.99f;
    __syncthreads();

    int wid = t / 32, lane = t % 32;
    for (int h = wid; h < 12; h += 8) {
        float m = -1e30f;
        for (int j = lane; j < Nn; j += 32) m = fmaxf(m, la[h * LA_LD + j]);
#pragma unroll
        for (int o = 16; o; o >>= 1) m = fmaxf(m, __shfl_xor_sync(0xffffffffu, m, o));
        float sum = 0.f;
        for (int j = lane; j < Nn; j += 32) {
            float e = expf(la[h * LA_LD + j] - m) * wrow[j];
            la[h * LA_LD + j] = e;
            sum += e;
        }
#pragma unroll
        for (int o = 16; o; o >>= 1) sum += __shfl_xor_sync(0xffffffffu, sum, o);
        float inv = 1.0f / sum;
        float* grow = &g_a[(size_t)h * NNt + (size_t)i * Nn];
        for (int j = lane; j < Nn; j += 32) {
            float v = la[h * LA_LD + j] * inv;
            la[h * LA_LD + j] = v;
            grow[j] = v;
        }
    }
    __syncthreads();

    /* wmma: [16 x 768] @ [768 x 128], warp w covers cols w*16..+15 */
    FragC cf;
    wmma::fill_fragment(cf, 0.f);
    const float* zrow = z + (size_t)i * Nn * 128 + wid * 16;
    for (int k0 = 0; k0 < Nn; k0 += 8)
        mma3(cf, la + k0, LA_LD, zrow + (size_t)k0 * 128, 128);

    wmma::store_matrix_sync(outst + wid * 16, cf, 128, wmma::mem_row_major);
    __syncthreads();

    for (int idx = t; idx < 12 * 128; idx += 256) {
        int h = idx / 128, c = idx % 128;
        g_cat[(size_t)i * CATD + 576 + h * 128 + c] = outst[h * 128 + c];
    }
}

/* ------ K4: o / o_pt via 3xtf32 wmma: per head [768 x 48] = a @ vc ------- */
__global__ __launch_bounds__(96) void k_out_ov()
{
    __shared__ float st[16 * 48];
    int i0 = blockIdx.x * 16, h = blockIdx.y;
    int t = threadIdx.x, w = t / 32;

    FragC cf;
    wmma::fill_fragment(cf, 0.f);

    const float* arow = g_a + (size_t)h * NNt + (size_t)i0 * Nn;
    const float* vcb  = g_vc + (size_t)h * Nn * 48 + w * 16;

    for (int k0 = 0; k0 < Nn; k0 += 8)
        mma3(cf, arow + k0, Nn, vcb + (size_t)k0 * 48, 48);

    wmma::store_matrix_sync(st + w * 16, cf, 48, wmma::mem_row_major);
    __syncthreads();

    for (int idx = t; idx < 16 * 40; idx += 96) {
        int r = idx / 40, c = idx % 40;
        float val = st[r * 48 + c];
        int i = i0 + r;
        if (c < 16) g_cat[(size_t)i * CATD + h * 16 + c] = val;
        else        g_ptg[(i * 12 + h) * 24 + (c - 16)]  = val;
    }
}

/* --------- K4b: frame-inverse rotation of o_pt + norms ------------------- */
__global__ __launch_bounds__(96) void k_ptfinish(const float* __restrict__ rot,
                                                 const float* __restrict__ trans)
{
    int i = blockIdx.x, t = threadIdx.x;
    int h = t / 8, p = t % 8;
    const float* pt = &g_ptg[(i * 12 + h) * 24 + p * 3];
    float gx = pt[0] - trans[i*3+0];
    float gy = pt[1] - trans[i*3+1];
    float gz = pt[2] - trans[i*3+2];
    const float* R = &rot[i*9];
    float lx = R[0]*gx + R[3]*gy + R[6]*gz;
    float ly = R[1]*gx + R[4]*gy + R[7]*gz;
    float lz = R[2]*gx + R[5]*gy + R[8]*gz;
    float nrm = sqrtf(lx*lx + ly*ly + lz*lz + 1e-8f);
    size_t base = (size_t)i * CATD;
    int hp = h * 8 + p;
    g_cat[base + 192 + hp] = lx;
    g_cat[base + 288 + hp] = ly;
    g_cat[base + 384 + hp] = lz;
    g_cat[base + 480 + hp] = nrm;
}

/* --------- K6: final GEMM 768 x 384 x 2112 via 3xtf32 wmma --------------- */
__global__ __launch_bounds__(256) void k_final(float* __restrict__ out,
                                               const float* __restrict__ W_out,
                                               const float* __restrict__ b_out)
{
    __shared__ float A_s[64 * 20];          /* [m][k], lda=20 */
    __shared__ float B_s[16 * 36];          /* [k][n], ldb=36 */
    __shared__ float st[8 * 256];
    int i0 = blockIdx.y * 64, n0 = blockIdx.x * 32;
    int t = threadIdx.x, w = t / 32;
    int wm = w % 4, wn = w / 4;

    FragC cf;
    wmma::fill_fragment(cf, 0.f);

    for (int k0 = 0; k0 < CATD; k0 += 16) {
        __syncthreads();
        { int r = t / 4, kc = (t % 4) * 4;
          *(float4*)&A_s[r * 20 + kc] =
              *(const float4*)&g_cat[(size_t)(i0 + r) * CATD + k0 + kc]; }
        if (t < 128) {
            int r = t / 8, c = (t % 8) * 4;
            *(float4*)&B_s[r * 36 + c] =
                *(const float4*)&W_out[(size_t)(k0 + r) * 384 + n0 + c];
        }
        __syncthreads();
#pragma unroll
        for (int kk = 0; kk < 16; kk += 8)
            mma3(cf, A_s + wm * 16 * 20 + kk, 20, B_s + kk * 36 + wn * 16, 36);
    }
    wmma::store_matrix_sync(&st[w * 256], cf, 16, wmma::mem_row_major);
    __syncthreads();

    for (int idx = t; idx < 64 * 32; idx += 256) {
        int r = idx / 32, c = idx % 32;
        int ww = (c / 16) * 4 + (r / 16);
        float val = st[ww * 256 + (r % 16) * 16 + (c % 16)] + b_out[n0 + c];
        out[(size_t)(i0 + r) * 384 + n0 + c] = val;
    }
}

/* ------------------------------- launch ---------------------------------- */
extern "C" void kernel_launch(void* const* d_in, const int* in_sizes, int n_in,
                              void* d_out, int out_size)
{
    const float* s     = (const float*)d_in[0];
    const float* z     = (const float*)d_in[1];
    const float* rot   = (const float*)d_in[2];
    const float* trans = (const float*)d_in[3];
    const float* mask  = (const float*)d_in[4];
    const float* ss    = (const float*)d_in[5];
    const float* W_q   = (const float*)d_in[6];
    const float* b_q   = (const float*)d_in[7];
    const float* W_kv  = (const float*)d_in[8];
    const float* b_kv  = (const float*)d_in[9];
    const float* W_qp  = (const float*)d_in[10];
    const float* b_qp  = (const float*)d_in[11];
    const float* W_kvp = (const float*)d_in[12];
    const float* b_kvp = (const float*)d_in[13];
    const float* W_b   = (const float*)d_in[14];
    const float* b_b   = (const float*)d_in[15];
    const float* hwts  = (const float*)d_in[16];
    const float* W_out = (const float*)d_in[17];
    const float* b_out = (const float*)d_in[18];
    float* out = (float*)d_out;

    static const size_t SOFT_DSM = (16 * LA_LD + Nn + 16 * 128) * sizeof(float);
    cudaFuncSetAttribute(k_soft_opair,
                         cudaFuncAttributeMaxDynamicSharedMemorySize,
                         (int)SOFT_DSM);

    k_pack<<<(384 * PROJ + 255) / 256, 256>>>(W_q, W_kv, W_qp, W_kvp,
                                              b_q, b_kv, b_qp, b_kvp);
    { dim3 g(PROJ / 64, Nn / 64); k_proj_gemm<<<g, 256>>>(s); }
    k_reshape<<<Nn, 192>>>(rot, trans);
    { dim3 g(Nn / 64, Nn / 64, 12); k_logits<<<g, 256>>>(mask, hwts, b_b); }
    k_bias_mma<<<NNt / 128, 256>>>(z, W_b);
    k_soft_opair<<<Nn, 256, SOFT_DSM>>>(z, ss);
    { dim3 g(Nn / 16, 12); k_out_ov<<<g, 96>>>(); }
    k_ptfinish<<<Nn, 96>>>(rot, trans);
    { dim3 g(384 / 32, Nn / 64); k_final<<<g, 256>>>(out, W_out, b_out); }
}

// round 14
// speedup vs baseline: 1.1675x; 1.1675x over previous
#include <cuda_runtime.h>
#include <mma.h>
#include <math.h>
#include <cstdint>

using namespace nvcuda;

#define Nn   768
#define NNt  (768*768)
#define PROJ 1152
#define CATD 2112

#define RS48 0.14433756729740643f   /* 1/sqrt(48) */
#define RS3  0.5773502691896258f    /* 1/sqrt(3)  */
#define RS54 0.13608276348795434f   /* 1/sqrt(54) */

/* ------------------------- scratch (device globals) ---------------------- */
__device__ float g_Wpack[384 * PROJ];
__device__ float g_bpack[PROJ];
__device__ float g_proj[Nn * PROJ];
__device__ float g_q [Nn * 192];
__device__ float g_k [Nn * 192];
__device__ float g_qp[Nn * 144];
__device__ float g_kp[Nn * 144];
__device__ float g_vc[12 * Nn * 48];        /* packed v(16) || vp(24) || pad8 */
__device__ float g_a [(size_t)12 * NNt];    /* logits -> attn (28.3 MB) */
__device__ float g_ptg[Nn * 12 * 24];       /* o_pt in global frame */
__device__ float g_cat[(size_t)Nn * CATD];

/* ---------------- 3xTF32 split-precision MMA helper ---------------------- */
typedef wmma::fragment<wmma::matrix_a, 16, 16, 8, wmma::precision::tf32, wmma::row_major> FragA;
typedef wmma::fragment<wmma::matrix_b, 16, 16, 8, wmma::precision::tf32, wmma::row_major> FragB;
typedef wmma::fragment<wmma::accumulator, 16, 16, 8, float> FragC;

__device__ __forceinline__ void mma3(FragC& cf,
                                     const float* aptr, int lda,
                                     const float* bptr, int ldb)
{
    FragA ah, al;
    FragB bh, bl;
    wmma::load_matrix_sync(ah, aptr, lda);
    wmma::load_matrix_sync(bh, bptr, ldb);
#pragma unroll
    for (int e = 0; e < ah.num_elements; e++) {
        float v = ah.x[e];
        float h = wmma::__float_to_tf32(v);
        ah.x[e] = h;
        al.x[e] = wmma::__float_to_tf32(v - h);
    }
#pragma unroll
    for (int e = 0; e < bh.num_elements; e++) {
        float v = bh.x[e];
        float h = wmma::__float_to_tf32(v);
        bh.x[e] = h;
        bl.x[e] = wmma::__float_to_tf32(v - h);
    }
    wmma::mma_sync(cf, ah, bl, cf);
    wmma::mma_sync(cf, al, bh, cf);
    wmma::mma_sync(cf, ah, bh, cf);
}

/* ------------------------- K0: pack projection weights ------------------- */
__global__ void k_pack(const float* __restrict__ Wq,  const float* __restrict__ Wkv,
                       const float* __restrict__ Wqp, const float* __restrict__ Wkvp,
                       const float* __restrict__ bq,  const float* __restrict__ bkv,
                       const float* __restrict__ bqp, const float* __restrict__ bkvp)
{
    int idx = blockIdx.x * blockDim.x + threadIdx.x;
    if (idx < 384 * PROJ) {
        int r = idx / PROJ, o = idx % PROJ;
        float v;
        if      (o < 192) v = Wq  [r * 192 + o];
        else if (o < 576) v = Wkv [r * 384 + (o - 192)];
        else if (o < 720) v = Wqp [r * 144 + (o - 576)];
        else              v = Wkvp[r * 432 + (o - 720)];
        g_Wpack[idx] = v;
    }
    if (idx < PROJ) {
        int o = idx;
        float v;
        if      (o < 192) v = bq  [o];
        else if (o < 576) v = bkv [o - 192];
        else if (o < 720) v = bqp [o - 576];
        else              v = bkvp[o - 720];
        g_bpack[o] = v;
    }
}

/* ------------------- K1: projection GEMM 768 x 1152 x 384 (fp32) --------- */
__global__ __launch_bounds__(256) void k_proj_gemm(const float* __restrict__ s)
{
    __shared__ float s_t[16][65];
    __shared__ float w_t[16][64];
    int o0 = blockIdx.x * 64, i0 = blockIdx.y * 64;
    int t  = threadIdx.x;
    int tx = t % 16, ty = t / 16;
    float acc[4][4];
#pragma unroll
    for (int a = 0; a < 4; a++)
#pragma unroll
        for (int b = 0; b < 4; b++) acc[a][b] = 0.f;

    for (int k0 = 0; k0 < 384; k0 += 16) {
        { int ii = t / 4, kc = (t % 4) * 4;
          float4 sv = *(const float4*)&s[(size_t)(i0 + ii) * 384 + k0 + kc];
          s_t[kc + 0][ii] = sv.x; s_t[kc + 1][ii] = sv.y;
          s_t[kc + 2][ii] = sv.z; s_t[kc + 3][ii] = sv.w; }
        { int kc = t / 16, oo = (t % 16) * 4;
          *(float4*)&w_t[kc][oo] =
              *(const float4*)&g_Wpack[(size_t)(k0 + kc) * PROJ + o0 + oo]; }
        __syncthreads();
#pragma unroll
        for (int kc = 0; kc < 16; kc++) {
            float sv[4];
#pragma unroll
            for (int a = 0; a < 4; a++) sv[a] = s_t[kc][ty * 4 + a];
            float4 w4 = *(float4*)&w_t[kc][tx * 4];
            float wv[4] = {w4.x, w4.y, w4.z, w4.w};
#pragma unroll
            for (int a = 0; a < 4; a++)
#pragma unroll
                for (int b = 0; b < 4; b++) acc[a][b] += sv[a] * wv[b];
        }
        __syncthreads();
    }
#pragma unroll
    for (int a = 0; a < 4; a++) {
        float4 o4;
        o4.x = acc[a][0] + g_bpack[o0 + tx * 4 + 0];
        o4.y = acc[a][1] + g_bpack[o0 + tx * 4 + 1];
        o4.z = acc[a][2] + g_bpack[o0 + tx * 4 + 2];
        o4.w = acc[a][3] + g_bpack[o0 + tx * 4 + 3];
        *(float4*)&g_proj[(size_t)(i0 + ty * 4 + a) * PROJ + o0 + tx * 4] = o4;
    }
}

/* -------------- K1b: reshape + rigid-frame rotation of points ------------ */
__global__ __launch_bounds__(192) void k_reshape(const float* __restrict__ rot,
                                                 const float* __restrict__ trans)
{
    int i = blockIdx.x, t = threadIdx.x;
    __shared__ float pr[PROJ];
    for (int idx = t; idx < PROJ; idx += 192) pr[idx] = g_proj[(size_t)i * PROJ + idx];
    __syncthreads();

    g_q[(size_t)i * 192 + t] = pr[t];
    for (int o = t; o < 384; o += 192) {
        int h = o / 32, w = o % 32;
        float v = pr[192 + o];
        if (w < 16) g_k[(size_t)i * 192 + h * 16 + w] = v;
        else        g_vc[(size_t)(h * Nn + i) * 48 + (w - 16)] = v;
    }
    for (int o = t; o < 96; o += 192) {
        int h = o / 8, c = 40 + (o % 8);
        g_vc[(size_t)(h * Nn + i) * 48 + c] = 0.f;
    }
    float R0 = rot[i*9+0], R1 = rot[i*9+1], R2 = rot[i*9+2];
    float R3 = rot[i*9+3], R4 = rot[i*9+4], R5 = rot[i*9+5];
    float R6 = rot[i*9+6], R7 = rot[i*9+7], R8 = rot[i*9+8];
    float T0 = trans[i*3+0], T1 = trans[i*3+1], T2 = trans[i*3+2];

    if (t < 48) {
        float v0 = pr[576 + t], v1 = pr[624 + t], v2 = pr[672 + t];
        float x = R0*v0 + R1*v1 + R2*v2 + T0;
        float y = R3*v0 + R4*v1 + R5*v2 + T1;
        float z = R6*v0 + R7*v1 + R8*v2 + T2;
        int base = i * 144 + t * 3;
        g_qp[base] = x; g_qp[base+1] = y; g_qp[base+2] = z;
    }
    if (t < 144) {
        float v0 = pr[720 + t], v1 = pr[864 + t], v2 = pr[1008 + t];
        float x = R0*v0 + R1*v1 + R2*v2 + T0;
        float y = R3*v0 + R4*v1 + R5*v2 + T1;
        float z = R6*v0 + R7*v1 + R8*v2 + T2;
        int h = t / 12, r = t % 12;
        if (r < 4) {
            int base = i * 144 + (h * 4 + r) * 3;
            g_kp[base] = x; g_kp[base+1] = y; g_kp[base+2] = z;
        } else {
            int base = (h * Nn + i) * 48 + 16 + (r - 4) * 3;
            g_vc[base] = x; g_vc[base+1] = y; g_vc[base+2] = z;
        }
    }
}

/* ---- K2a: logits = qk*rs48 + pt + mask + rs3*b_b   (64x64xh tiles) ------ */
__global__ __launch_bounds__(256) void k_logits(const float* __restrict__ mask,
                                                const float* __restrict__ hwraw,
                                                const float* __restrict__ b_b)
{
    __shared__ float q_sT[16][64], k_sT[16][64];
    __shared__ float qp_sT[12][64], kp_sT[12][64];
    __shared__ float mi_s[64], mj_s[64];
    __shared__ float hw_sh, bb_sh;
    int h = blockIdx.z, i0 = blockIdx.y * 64, j0 = blockIdx.x * 64;
    int t = threadIdx.x;

    { int ii = t / 4, c0 = (t % 4) * 4;
      float4 qv = *(const float4*)&g_q[(size_t)(i0 + ii) * 192 + h * 16 + c0];
      q_sT[c0+0][ii] = qv.x; q_sT[c0+1][ii] = qv.y; q_sT[c0+2][ii] = qv.z; q_sT[c0+3][ii] = qv.w;
      float4 kv = *(const float4*)&g_k[(size_t)(j0 + ii) * 192 + h * 16 + c0];
      k_sT[c0+0][ii] = kv.x; k_sT[c0+1][ii] = kv.y; k_sT[c0+2][ii] = kv.z; k_sT[c0+3][ii] = kv.w; }
    if (t < 192) {
      int ii = t / 3, c0 = (t % 3) * 4;
      float4 qv = *(const float4*)&g_qp[(size_t)(i0 + ii) * 144 + h * 12 + c0];
      qp_sT[c0+0][ii] = qv.x; qp_sT[c0+1][ii] = qv.y; qp_sT[c0+2][ii] = qv.z; qp_sT[c0+3][ii] = qv.w;
      float4 kv = *(const float4*)&g_kp[(size_t)(j0 + ii) * 144 + h * 12 + c0];
      kp_sT[c0+0][ii] = kv.x; kp_sT[c0+1][ii] = kv.y; kp_sT[c0+2][ii] = kv.z; kp_sT[c0+3][ii] = kv.w; }
    if (t < 64) { mi_s[t] = mask[i0 + t]; mj_s[t] = mask[j0 + t]; }
    if (t == 0) {
        hw_sh = log1pf(expf(hwraw[h])) * RS54;
        bb_sh = b_b[h] * RS3;
    }
    __syncthreads();

    int tx = t % 16, ty = t / 16;
    float acc[4][4], d2[4][4];
#pragma unroll
    for (int a = 0; a < 4; a++)
#pragma unroll
        for (int b = 0; b < 4; b++) { acc[a][b] = 0.f; d2[a][b] = 0.f; }

#pragma unroll
    for (int c = 0; c < 16; c++) {
        float qr[4];
#pragma unroll
        for (int a = 0; a < 4; a++) qr[a] = q_sT[c][ty * 4 + a];
        float4 k4 = *(float4*)&k_sT[c][tx * 4];
        float kr[4] = {k4.x, k4.y, k4.z, k4.w};
#pragma unroll
        for (int a = 0; a < 4; a++)
#pragma unroll
            for (int b = 0; b < 4; b++) acc[a][b] += qr[a] * kr[b];
    }
#pragma unroll
    for (int p = 0; p < 4; p++) {
        float qx[4], qy[4], qz[4], kx[4], ky[4], kz[4];
#pragma unroll
        for (int a = 0; a < 4; a++) {
            qx[a] = qp_sT[p*3+0][ty*4+a];
            qy[a] = qp_sT[p*3+1][ty*4+a];
            qz[a] = qp_sT[p*3+2][ty*4+a];
        }
#pragma unroll
        for (int b = 0; b < 4; b++) {
            kx[b] = kp_sT[p*3+0][tx*4+b];
            ky[b] = kp_sT[p*3+1][tx*4+b];
            kz[b] = kp_sT[p*3+2][tx*4+b];
        }
#pragma unroll
        for (int a = 0; a < 4; a++)
#pragma unroll
            for (int b = 0; b < 4; b++) {
                float dx = qx[a]-kx[b], dy = qy[a]-ky[b], dz = qz[a]-kz[b];
                d2[a][b] += dx*dx + dy*dy + dz*dz;
            }
    }
    float hw = hw_sh, bb = bb_sh;
#pragma unroll
    for (int a = 0; a < 4; a++) {
        float mi = mi_s[ty * 4 + a];
        float4 o4;
        o4.x = acc[a][0]*RS48 - 0.5f*hw*d2[a][0] + bb + 100000.0f*(mi*mj_s[tx*4+0] - 1.0f);
        o4.y = acc[a][1]*RS48 - 0.5f*hw*d2[a][1] + bb + 100000.0f*(mi*mj_s[tx*4+1] - 1.0f);
        o4.z = acc[a][2]*RS48 - 0.5f*hw*d2[a][2] + bb + 100000.0f*(mi*mj_s[tx*4+2] - 1.0f);
        o4.w = acc[a][3]*RS48 - 0.5f*hw*d2[a][3] + bb + 100000.0f*(mi*mj_s[tx*4+3] - 1.0f);
        *(float4*)&g_a[(size_t)h * NNt + (size_t)(i0 + ty*4 + a) * Nn + j0 + tx*4] = o4;
    }
}

/* ==== K3: FUSED bias(z@Wb) + weighted online-softmax + o_pair  ===========
   One block per i.  z[i] read from DRAM exactly once; double-buffered in
   smem via REGISTER-staged prefetch (no cp.async asm).                    */
#define JC   32
#define ZLD  132                      /* z chunk row stride (floats)      */
#define NCH  (Nn / JC)                /* 24 chunks                        */

__global__ __launch_bounds__(256) void k_flash(const float* __restrict__ z,
                                               const float* __restrict__ ss,
                                               const float* __restrict__ W_b)
{
    extern __shared__ float sm[];
    float* la    = sm;                       /* 12 x 768                  */
    float* zb    = la    + 12 * Nn;          /* 2 x JC x ZLD              */
    float* wb    = zb    + 2 * JC * ZLD;     /* 128 x 20                  */
    float* part  = wb    + 128 * 20;         /* 8 x 256                   */
    float* bi    = part  + 8 * 256;          /* JC x 20                   */
    float* ps    = bi    + JC * 20;          /* 12 x 33                   */
    float* wrow  = ps    + 12 * 33;          /* 768                       */
    float* m_sh  = wrow  + Nn;               /* 12                        */
    float* s_sh  = m_sh  + 12;               /* 12                        */
    float* sc_sh = s_sh  + 12;               /* 12                        */

    int i = blockIdx.x, t = threadIdx.x;
    const float* zrow = z + (size_t)i * Nn * 128;

    for (int idx = t; idx < 12 * Nn; idx += 256) {
        int h = idx / Nn, j = idx % Nn;
        la[idx] = g_a[(size_t)h * NNt + (size_t)i * Nn + j];
    }
    for (int j = t; j < Nn; j += 256)
        wrow[j] = expf(ss[(size_t)i * Nn + j]) - 0.99f;
    for (int idx = t; idx < 128 * 16; idx += 256) {
        int c = idx / 16, h = idx % 16;
        wb[c * 20 + h] = (h < 12) ? RS3 * W_b[c * 12 + h] : 0.f;
    }
    if (t < 12) { m_sh[t] = -1e30f; s_sh[t] = 0.f; }

    int c = t & 127, hg = t >> 7;
    float acc[6];
#pragma unroll
    for (int k = 0; k < 6; k++) acc[k] = 0.f;

    /* per-thread segment coordinates: 4 float4 segs covering 32x128 chunk */
    int jj_[4], c16_[4];
#pragma unroll
    for (int k2 = 0; k2 < 4; k2++) {
        int sseg = t + k2 * 256;
        jj_[k2]  = sseg >> 5;
        c16_[k2] = sseg & 31;
    }

    /* prefetch chunk 0 into registers */
    float4 pf[4];
#pragma unroll
    for (int k2 = 0; k2 < 4; k2++)
        pf[k2] = *(const float4*)(zrow + jj_[k2] * 128 + c16_[k2] * 4);

    int w = t >> 5, mt = w & 1, kq = w >> 1;

    for (int ch = 0; ch < NCH; ch++) {
        float* zs = zb + (ch & 1) * (JC * ZLD);

        /* store registers (chunk ch) into smem buffer ch&1 */
#pragma unroll
        for (int k2 = 0; k2 < 4; k2++)
            *(float4*)(zs + jj_[k2] * ZLD + c16_[k2] * 4) = pf[k2];

        /* issue prefetch of chunk ch+1 (in flight during compute) */
        if (ch + 1 < NCH) {
            const float* src = zrow + (size_t)(ch + 1) * JC * 128;
#pragma unroll
            for (int k2 = 0; k2 < 4; k2++)
                pf[k2] = *(const float4*)(src + jj_[k2] * 128 + c16_[k2] * 4);
        }
        __syncthreads();

        /* ---- bias wmma: warp w -> m-tile mt, k-quarter kq (tf32 1x) ---- */
        {
            FragA af; FragB bf; FragC cfb;
            wmma::fill_fragment(cfb, 0.f);
#pragma unroll
            for (int kk = 0; kk < 4; kk++) {
                int k0 = (kq * 4 + kk) * 8;
                wmma::load_matrix_sync(af, zs + mt * 16 * ZLD + k0, ZLD);
#pragma unroll
                for (int e = 0; e < af.num_elements; e++)
                    af.x[e] = wmma::__float_to_tf32(af.x[e]);
                wmma::load_matrix_sync(bf, wb + k0 * 20, 20);
#pragma unroll
                for (int e = 0; e < bf.num_elements; e++)
                    bf.x[e] = wmma::__float_to_tf32(bf.x[e]);
                wmma::mma_sync(cfb, af, bf, cfb);
            }
            wmma::store_matrix_sync(part + w * 256, cfb, 16, wmma::mem_row_major);
        }
        __syncthreads();

        /* ---- reduce 4 k-quarters -> bi[j][h] ---- */
        for (int idx = t; idx < JC * 12; idx += 256) {
            int j = idx / 12, h = idx % 12;
            int jm = j >> 4, jr = j & 15;
            float v = part[(jm      ) * 256 + jr * 16 + h]
                    + part[(jm + 2  ) * 256 + jr * 16 + h]
                    + part[(jm + 4  ) * 256 + jr * 16 + h]
                    + part[(jm + 6  ) * 256 + jr * 16 + h];
            bi[j * 20 + h] = v;
        }
        __syncthreads();

        /* ---- scalar: add bias, chunk max, online update, p ---- */
        if (t < 192) {
            int h = t >> 4, l16 = t & 15;
            int j0 = l16, j1 = l16 + 16;
            int base = h * Nn + ch * JC;
            float L0 = la[base + j0] + bi[j0 * 20 + h];
            float L1 = la[base + j1] + bi[j1 * 20 + h];
            la[base + j0] = L0;
            la[base + j1] = L1;
            float mc = fmaxf(L0, L1);
#pragma unroll
            for (int o = 8; o; o >>= 1)
                mc = fmaxf(mc, __shfl_xor_sync(0xffffffffu, mc, o));
            float mold = m_sh[h];
            float mnew = fmaxf(mold, mc);
            float p0 = expf(L0 - mnew) * wrow[ch * JC + j0];
            float p1 = expf(L1 - mnew) * wrow[ch * JC + j1];
            ps[h * 33 + j0] = p0;
            ps[h * 33 + j1] = p1;
            float psum = p0 + p1;
#pragma unroll
            for (int o = 8; o; o >>= 1)
                psum += __shfl_xor_sync(0xffffffffu, psum, o);
            if (l16 == 0) {
                float sc = expf(mold - mnew);
                s_sh[h] = s_sh[h] * sc + psum;
                m_sh[h] = mnew;
                sc_sh[h] = sc;
            }
        }
        __syncthreads();

        /* ---- o_pair accumulate ---- */
        {
            float sc[6];
#pragma unroll
            for (int k = 0; k < 6; k++) sc[k] = sc_sh[hg * 6 + k];
#pragma unroll
            for (int k = 0; k < 6; k++) acc[k] *= sc[k];
#pragma unroll 4
            for (int j = 0; j < JC; j++) {
                float zv = zs[j * ZLD + c];
#pragma unroll
                for (int k = 0; k < 6; k++)
                    acc[k] += ps[(hg * 6 + k) * 33 + j] * zv;
            }
        }
        __syncthreads();
    }

    /* ---- epilogue ---- */
    if (t < 12) sc_sh[t] = 1.0f / s_sh[t];
    __syncthreads();

    for (int idx = t; idx < 12 * Nn; idx += 256) {
        int h = idx / Nn, j = idx % Nn;
        float a = expf(la[idx] - m_sh[h]) * wrow[j] * sc_sh[h];
        g_a[(size_t)h * NNt + (size_t)i * Nn + j] = a;
    }
    {
        size_t base = (size_t)i * CATD + 576;
#pragma unroll
        for (int k = 0; k < 6; k++)
            g_cat[base + (size_t)(hg * 6 + k) * 128 + c] = acc[k] * sc_sh[hg * 6 + k];
    }
}

#define FLASH_DSM ((12*Nn + 2*JC*ZLD + 128*20 + 8*256 + JC*20 + 12*33 + Nn + 36) * sizeof(float))

/* ------ K4: o / o_pt via 3xtf32 wmma: per head [768 x 48] = a @ vc ------- */
__global__ __launch_bounds__(96) void k_out_ov()
{
    __shared__ float st[16 * 48];
    int i0 = blockIdx.x * 16, h = blockIdx.y;
    int t = threadIdx.x, w = t / 32;

    FragC cf;
    wmma::fill_fragment(cf, 0.f);

    const float* arow = g_a + (size_t)h * NNt + (size_t)i0 * Nn;
    const float* vcb  = g_vc + (size_t)h * Nn * 48 + w * 16;

    for (int k0 = 0; k0 < Nn; k0 += 8)
        mma3(cf, arow + k0, Nn, vcb + (size_t)k0 * 48, 48);

    wmma::store_matrix_sync(st + w * 16, cf, 48, wmma::mem_row_major);
    __syncthreads();

    for (int idx = t; idx < 16 * 40; idx += 96) {
        int r = idx / 40, c = idx % 40;
        float val = st[r * 48 + c];
        int i = i0 + r;
        if (c < 16) g_cat[(size_t)i * CATD + h * 16 + c] = val;
        else        g_ptg[(i * 12 + h) * 24 + (c - 16)]  = val;
    }
}

/* --------- K4b: frame-inverse rotation of o_pt + norms ------------------- */
__global__ __launch_bounds__(96) void k_ptfinish(const float* __restrict__ rot,
                                                 const float* __restrict__ trans)
{
    int i = blockIdx.x, t = threadIdx.x;
    int h = t / 8, p = t % 8;
    const float* pt = &g_ptg[(i * 12 + h) * 24 + p * 3];
    float gx = pt[0] - trans[i*3+0];
    float gy = pt[1] - trans[i*3+1];
    float gz = pt[2] - trans[i*3+2];
    const float* R = &rot[i*9];
    float lx = R[0]*gx + R[3]*gy + R[6]*gz;
    float ly = R[1]*gx + R[4]*gy + R[7]*gz;
    float lz = R[2]*gx + R[5]*gy + R[8]*gz;
    float nrm = sqrtf(lx*lx + ly*ly + lz*lz + 1e-8f);
    size_t base = (size_t)i * CATD;
    int hp = h * 8 + p;
    g_cat[base + 192 + hp] = lx;
    g_cat[base + 288 + hp] = ly;
    g_cat[base + 384 + hp] = lz;
    g_cat[base + 480 + hp] = nrm;
}

/* --------- K6: final GEMM 768 x 384 x 2112 via 3xtf32 wmma --------------- */
__global__ __launch_bounds__(256) void k_final(float* __restrict__ out,
                                               const float* __restrict__ W_out,
                                               const float* __restrict__ b_out)
{
    __shared__ float A_s[64 * 20];
    __shared__ float B_s[16 * 36];
    __shared__ float st[8 * 256];
    int i0 = blockIdx.y * 64, n0 = blockIdx.x * 32;
    int t = threadIdx.x, w = t / 32;
    int wm = w % 4, wn = w / 4;

    FragC cf;
    wmma::fill_fragment(cf, 0.f);

    for (int k0 = 0; k0 < CATD; k0 += 16) {
        __syncthreads();
        { int r = t / 4, kc = (t % 4) * 4;
          *(float4*)&A_s[r * 20 + kc] =
              *(const float4*)&g_cat[(size_t)(i0 + r) * CATD + k0 + kc]; }
        if (t < 128) {
            int r = t / 8, c = (t % 8) * 4;
            *(float4*)&B_s[r * 36 + c] =
                *(const float4*)&W_out[(size_t)(k0 + r) * 384 + n0 + c];
        }
        __syncthreads();
#pragma unroll
        for (int kk = 0; kk < 16; kk += 8)
            mma3(cf, A_s + wm * 16 * 20 + kk, 20, B_s + kk * 36 + wn * 16, 36);
    }
    wmma::store_matrix_sync(&st[w * 256], cf, 16, wmma::mem_row_major);
    __syncthreads();

    for (int idx = t; idx < 64 * 32; idx += 256) {
        int r = idx / 32, c = idx % 32;
        int ww = (c / 16) * 4 + (r / 16);
        float val = st[ww * 256 + (r % 16) * 16 + (c % 16)] + b_out[n0 + c];
        out[(size_t)(i0 + r) * 384 + n0 + c] = val;
    }
}

/* ------------------------------- launch ---------------------------------- */
extern "C" void kernel_launch(void* const* d_in, const int* in_sizes, int n_in,
                              void* d_out, int out_size)
{
    const float* s     = (const float*)d_in[0];
    const float* z     = (const float*)d_in[1];
    const float* rot   = (const float*)d_in[2];
    const float* trans = (const float*)d_in[3];
    const float* mask  = (const float*)d_in[4];
    const float* ss    = (const float*)d_in[5];
    const float* W_q   = (const float*)d_in[6];
    const float* b_q   = (const float*)d_in[7];
    const float* W_kv  = (const float*)d_in[8];
    const float* b_kv  = (const float*)d_in[9];
    const float* W_qp  = (const float*)d_in[10];
    const float* b_qp  = (const float*)d_in[11];
    const float* W_kvp = (const float*)d_in[12];
    const float* b_kvp = (const float*)d_in[13];
    const float* W_b   = (const float*)d_in[14];
    const float* b_b   = (const float*)d_in[15];
    const float* hwts  = (const float*)d_in[16];
    const float* W_out = (const float*)d_in[17];
    const float* b_out = (const float*)d_in[18];
    float* out = (float*)d_out;

    cudaFuncSetAttribute(k_flash,
                         cudaFuncAttributeMaxDynamicSharedMemorySize,
                         (int)FLASH_DSM);

    k_pack<<<(384 * PROJ + 255) / 256, 256>>>(W_q, W_kv, W_qp, W_kvp,
                                              b_q, b_kv, b_qp, b_kvp);
    { dim3 g(PROJ / 64, Nn / 64); k_proj_gemm<<<g, 256>>>(s); }
    k_reshape<<<Nn, 192>>>(rot, trans);
    { dim3 g(Nn / 64, Nn / 64, 12); k_logits<<<g, 256>>>(mask, hwts, b_b); }
    k_flash<<<Nn, 256, FLASH_DSM>>>(z, ss, W_b);
    { dim3 g(Nn / 16, 12); k_out_ov<<<g, 96>>>(); }
    k_ptfinish<<<Nn, 96>>>(rot, trans);
    { dim3 g(384 / 32, Nn / 64); k_final<<<g, 256>>>(out, W_out, b_out); }
}